// round 2
// baseline (speedup 1.0000x reference)
#include <cuda_runtime.h>

// Problem constants
#define Bq 2
#define Sq 2048
#define Eq 768
#define Hq 12
#define Gq 4
#define Dq 64
#define Tq 512   // Sq / Gq

// ---------------------------------------------------------------------------
// Scratch (device globals; no dynamic allocation allowed)
// ---------------------------------------------------------------------------
__device__ float g_qproj[Bq*Sq*Eq];          // [b][s][e]
__device__ float g_kproj[Bq*Sq*Eq];
__device__ float g_vproj[Bq*Sq*Eq];
__device__ float g_qg  [Gq*Bq*Tq*Eq];        // [g][b][t][e]
__device__ float g_qi  [Gq*Bq*Tq*Eq];
__device__ float g_ki  [(size_t)Gq*Bq*Sq*Eq];// [g][b][s][e]
__device__ float g_vi  [(size_t)Gq*Bq*Sq*Eq];
__device__ float g_ctx [Gq*Bq*Tq*Eq];
__device__ float g_outg[Gq*Bq*Tq*Eq];

// ---------------------------------------------------------------------------
// Generic fp32 GEMM: C[m][n] = sum_k A[m][k] * W[n][k] + bias[n]
// Batched over blockIdx.z with per-operand strides.
// Block tile 64x64, 256 threads, 4x4 per-thread register tile, k-chunk 16.
// Requires M % 64 == 0, N % 64 == 0, K % 16 == 0 (all true here).
// ---------------------------------------------------------------------------
__global__ __launch_bounds__(256)
void gemm_bias_kernel(const float* __restrict__ A, size_t sA,
                      const float* __restrict__ W, size_t sW,
                      const float* __restrict__ bias, size_t sB,
                      float* __restrict__ C, size_t sC,
                      int M, int N, int K)
{
    __shared__ float As[16][68];   // k-major, padded: row stride 68 (16B-aligned)
    __shared__ float Ws[16][68];

    const int z = blockIdx.z;
    A    += (size_t)z * sA;
    W    += (size_t)z * sW;
    bias += (size_t)z * sB;
    C    += (size_t)z * sC;

    const int m0 = blockIdx.y * 64;
    const int n0 = blockIdx.x * 64;
    const int tid = threadIdx.x;
    const int tx = tid & 15;       // n micro
    const int ty = tid >> 4;       // m micro

    float acc[4][4] = {};

    for (int k0 = 0; k0 < K; k0 += 16) {
        #pragma unroll
        for (int i = 0; i < 4; i++) {
            int idx = tid + i * 256;        // 0..1023
            int kk = idx & 15;
            int r  = idx >> 4;              // 0..63
            As[kk][r] = A[(size_t)(m0 + r) * K + k0 + kk];
            Ws[kk][r] = W[(size_t)(n0 + r) * K + k0 + kk];
        }
        __syncthreads();

        #pragma unroll
        for (int kk = 0; kk < 16; kk++) {
            float4 a4 = *(const float4*)&As[kk][ty * 4];
            float4 b4 = *(const float4*)&Ws[kk][tx * 4];
            float a[4] = {a4.x, a4.y, a4.z, a4.w};
            float b[4] = {b4.x, b4.y, b4.z, b4.w};
            #pragma unroll
            for (int i = 0; i < 4; i++)
                #pragma unroll
                for (int j = 0; j < 4; j++)
                    acc[i][j] += a[i] * b[j];
        }
        __syncthreads();
    }

    #pragma unroll
    for (int i = 0; i < 4; i++) {
        int m = m0 + ty * 4 + i;
        #pragma unroll
        for (int j = 0; j < 4; j++) {
            int n = n0 + tx * 4 + j;
            C[(size_t)m * N + n] = acc[i][j] + bias[n];
        }
    }
}

// ---------------------------------------------------------------------------
// Flash attention (fp32, online softmax).
// grid: (T/64, H, G*B). block: 256 threads (16x16).
// Each block: 64-query tile for one (g,b,h); loop over S in 32-key chunks.
// Thread owns 4 q-rows (ty*4..+3); score cols {tx, tx+16}; out d-cols tx*4..+3.
// ---------------------------------------------------------------------------
__global__ __launch_bounds__(256)
void flash_kernel(const float* __restrict__ qi,
                  const float* __restrict__ ki,
                  const float* __restrict__ vi,
                  float* __restrict__ ctx)
{
    __shared__ float Qs[64][68];
    __shared__ float Ks[32][68];
    __shared__ float Vs[32][68];
    __shared__ float Ps[64][36];

    const int zz = blockIdx.z;                 // g*B + b  (matches [g][b] layout)
    const int h  = blockIdx.y;
    const int t0 = blockIdx.x * 64;
    const size_t qbase = ((size_t)zz * Tq + t0) * Eq + (size_t)h * Dq;
    const size_t kbase = (size_t)zz * Sq * Eq + (size_t)h * Dq;

    const int tid = threadIdx.x;
    const int tx = tid & 15;
    const int ty = tid >> 4;

    // Load Q tile [64 x 64]
    #pragma unroll
    for (int i = 0; i < 16; i++) {
        int idx = tid + i * 256;
        int d = idx & 63;
        int r = idx >> 6;
        Qs[r][d] = qi[qbase + (size_t)r * Eq + d];
    }

    float m[4], l[4], acc[4][4];
    #pragma unroll
    for (int i = 0; i < 4; i++) {
        m[i] = -1e30f; l[i] = 0.f;
        #pragma unroll
        for (int j = 0; j < 4; j++) acc[i][j] = 0.f;
    }
    const float scale = 0.125f;   // 1/sqrt(64)

    for (int s0 = 0; s0 < Sq; s0 += 32) {
        __syncthreads();   // protect Ks/Vs/Ps from previous iteration's readers
        #pragma unroll
        for (int i = 0; i < 8; i++) {
            int idx = tid + i * 256;
            int d = idx & 63;
            int c = idx >> 6;
            size_t go = kbase + (size_t)(s0 + c) * Eq + d;
            Ks[c][d] = ki[go];
            Vs[c][d] = vi[go];
        }
        __syncthreads();

        // Scores: s[i][j] = <Q[row], K[col]>
        float sc[4][2] = {};
        #pragma unroll
        for (int d4 = 0; d4 < 16; d4++) {
            float4 k0 = *(const float4*)&Ks[tx][d4 * 4];
            float4 k1 = *(const float4*)&Ks[tx + 16][d4 * 4];
            #pragma unroll
            for (int i = 0; i < 4; i++) {
                float4 q4 = *(const float4*)&Qs[ty * 4 + i][d4 * 4];
                sc[i][0] += q4.x*k0.x + q4.y*k0.y + q4.z*k0.z + q4.w*k0.w;
                sc[i][1] += q4.x*k1.x + q4.y*k1.y + q4.z*k1.z + q4.w*k1.w;
            }
        }

        // Online softmax update (row reductions across the 16 tx lanes)
        #pragma unroll
        for (int i = 0; i < 4; i++) {
            float s0v = sc[i][0] * scale;
            float s1v = sc[i][1] * scale;
            float rmax = fmaxf(s0v, s1v);
            #pragma unroll
            for (int off = 8; off; off >>= 1)
                rmax = fmaxf(rmax, __shfl_xor_sync(0xffffffffu, rmax, off));
            float mn = fmaxf(m[i], rmax);
            float corr = __expf(m[i] - mn);
            m[i] = mn;
            float p0 = __expf(s0v - mn);
            float p1 = __expf(s1v - mn);
            float rs = p0 + p1;
            #pragma unroll
            for (int off = 8; off; off >>= 1)
                rs += __shfl_xor_sync(0xffffffffu, rs, off);
            l[i] = l[i] * corr + rs;
            #pragma unroll
            for (int j = 0; j < 4; j++) acc[i][j] *= corr;
            Ps[ty * 4 + i][tx]      = p0;
            Ps[ty * 4 + i][tx + 16] = p1;
        }
        __syncthreads();

        // PV: acc[i][:] += P[row][c] * V[c][d-cols]
        #pragma unroll
        for (int c = 0; c < 32; c++) {
            float4 v4 = *(const float4*)&Vs[c][tx * 4];
            #pragma unroll
            for (int i = 0; i < 4; i++) {
                float p = Ps[ty * 4 + i][c];
                acc[i][0] += p * v4.x;
                acc[i][1] += p * v4.y;
                acc[i][2] += p * v4.z;
                acc[i][3] += p * v4.w;
            }
        }
    }

    #pragma unroll
    for (int i = 0; i < 4; i++) {
        float inv = 1.0f / l[i];
        #pragma unroll
        for (int j = 0; j < 4; j++)
            ctx[qbase + (size_t)(ty * 4 + i) * Eq + tx * 4 + j] = acc[i][j] * inv;
    }
}

// ---------------------------------------------------------------------------
// Permutes: interleaved group split / merge (s = t*G + g)
// ---------------------------------------------------------------------------
__global__ void group_q_kernel(const float* __restrict__ src, float* __restrict__ dst)
{
    int idx = blockIdx.x * 256 + threadIdx.x;   // over G*B*T*E (dst index)
    int e = idx % Eq;
    int r = idx / Eq;            // (g*B+b)*T + t
    int t = r % Tq;
    int gb = r / Tq;
    int b = gb % Bq;
    int g = gb / Bq;
    dst[idx] = src[((size_t)b * Sq + (size_t)t * Gq + g) * Eq + e];
}

__global__ void ungroup_kernel(const float* __restrict__ src, float* __restrict__ dst)
{
    int idx = blockIdx.x * 256 + threadIdx.x;   // over B*S*E (dst index)
    int e = idx % Eq;
    int r = idx / Eq;            // b*S + s
    int s = r % Sq;
    int b = r / Sq;
    int t = s / Gq;
    int g = s % Gq;
    dst[idx] = src[(((size_t)(g * Bq + b)) * Tq + t) * Eq + e];
}

// ---------------------------------------------------------------------------
// Launch
// ---------------------------------------------------------------------------
extern "C" void kernel_launch(void* const* d_in, const int* in_sizes, int n_in,
                              void* d_out, int out_size)
{
    const float* query = (const float*)d_in[0];
    const float* key_  = (const float*)d_in[1];
    const float* value = (const float*)d_in[2];
    const float* Wqg   = (const float*)d_in[3];
    const float* bqg   = (const float*)d_in[4];
    const float* Wk    = (const float*)d_in[5];
    const float* bk    = (const float*)d_in[6];
    const float* Wv    = (const float*)d_in[7];
    const float* bv    = (const float*)d_in[8];
    const float* Wq_in = (const float*)d_in[9];
    const float* bq_in = (const float*)d_in[10];
    const float* Wk_in = (const float*)d_in[11];
    const float* bk_in = (const float*)d_in[12];
    const float* Wv_in = (const float*)d_in[13];
    const float* bv_in = (const float*)d_in[14];
    const float* Wout  = (const float*)d_in[15];
    const float* bout  = (const float*)d_in[16];
    float* out = (float*)d_out;

    float *qproj, *kproj, *vproj, *qg, *qiP, *kiP, *viP, *ctx, *outg;
    cudaGetSymbolAddress((void**)&qproj, g_qproj);
    cudaGetSymbolAddress((void**)&kproj, g_kproj);
    cudaGetSymbolAddress((void**)&vproj, g_vproj);
    cudaGetSymbolAddress((void**)&qg,    g_qg);
    cudaGetSymbolAddress((void**)&qiP,   g_qi);
    cudaGetSymbolAddress((void**)&kiP,   g_ki);
    cudaGetSymbolAddress((void**)&viP,   g_vi);
    cudaGetSymbolAddress((void**)&ctx,   g_ctx);
    cudaGetSymbolAddress((void**)&outg,  g_outg);

    const dim3 blk(256);
    const size_t EE  = (size_t)Eq * Eq;
    const size_t BTE = (size_t)Bq * Tq * Eq;
    const size_t BSE = (size_t)Bq * Sq * Eq;

    // 1) Outer projections: [B*S, E] x [E, E]^T
    dim3 gproj(Eq / 64, (Bq * Sq) / 64, 1);
    gemm_bias_kernel<<<gproj, blk>>>(query, 0, Wqg, 0, bqg, 0, qproj, 0, Bq*Sq, Eq, Eq);
    gemm_bias_kernel<<<gproj, blk>>>(key_,  0, Wk,  0, bk,  0, kproj, 0, Bq*Sq, Eq, Eq);
    gemm_bias_kernel<<<gproj, blk>>>(value, 0, Wv,  0, bv,  0, vproj, 0, Bq*Sq, Eq, Eq);

    // 2) Gather interleaved query groups: qg[g][b][t] = qproj[b][t*G+g]
    group_q_kernel<<<(Gq * Bq * Tq * Eq) / 256, blk>>>(qproj, qg);

    // 3) Per-group inner projections
    dim3 gqi(Eq / 64, (Bq * Tq) / 64, Gq);
    gemm_bias_kernel<<<gqi, blk>>>(qg, BTE, Wq_in, EE, bq_in, Eq, qiP, BTE, Bq*Tq, Eq, Eq);
    dim3 gki(Eq / 64, (Bq * Sq) / 64, Gq);
    gemm_bias_kernel<<<gki, blk>>>(kproj, 0, Wk_in, EE, bk_in, Eq, kiP, BSE, Bq*Sq, Eq, Eq);
    gemm_bias_kernel<<<gki, blk>>>(vproj, 0, Wv_in, EE, bv_in, Eq, viP, BSE, Bq*Sq, Eq, Eq);

    // 4) Attention
    dim3 gfa(Tq / 64, Hq, Bq * Gq);
    flash_kernel<<<gfa, blk>>>(qiP, kiP, viP, ctx);

    // 5) Output projection + scatter back to sequence order
    gemm_bias_kernel<<<gqi, blk>>>(ctx, BTE, Wout, EE, bout, Eq, outg, BTE, Bq*Tq, Eq, Eq);
    ungroup_kernel<<<(Bq * Sq * Eq) / 256, blk>>>(outg, out);
}

// round 3
// speedup vs baseline: 2.9395x; 2.9395x over previous
#include <cuda_runtime.h>
#include <cstdint>

// Problem constants
#define Bq 2
#define Sq 2048
#define Eq 768
#define Hq 12
#define Gq 4
#define Dq 64
#define Tq 512   // Sq / Gq

// ---------------------------------------------------------------------------
// Scratch (device globals; no dynamic allocation allowed)
// ---------------------------------------------------------------------------
__device__ float g_qproj[Bq*Sq*Eq];
__device__ float g_kproj[Bq*Sq*Eq];
__device__ float g_vproj[Bq*Sq*Eq];
__device__ float g_qg  [Gq*Bq*Tq*Eq];
__device__ float g_qi  [Gq*Bq*Tq*Eq];
__device__ float g_ki  [(size_t)Gq*Bq*Sq*Eq];
__device__ float g_vi  [(size_t)Gq*Bq*Sq*Eq];
__device__ float g_ctx [Gq*Bq*Tq*Eq];
__device__ float g_outg[Gq*Bq*Tq*Eq];

// ---------------------------------------------------------------------------
// tf32 helpers
// ---------------------------------------------------------------------------
__device__ __forceinline__ float f2tf32(float x) {
    uint32_t r;
    asm("cvt.rna.tf32.f32 %0, %1;" : "=r"(r) : "f"(x));
    return __uint_as_float(r);
}

__device__ __forceinline__ float4 f2tf32_4(float4 v) {
    return make_float4(f2tf32(v.x), f2tf32(v.y), f2tf32(v.z), f2tf32(v.w));
}

// D += A * B  (m16n8k8, tf32 inputs as f32 bit patterns, f32 accum)
__device__ __forceinline__ void mma_tf32(float (&d)[4], const float a[4], const float b[2]) {
    asm volatile(
        "mma.sync.aligned.m16n8k8.row.col.f32.tf32.tf32.f32 "
        "{%0,%1,%2,%3}, {%4,%5,%6,%7}, {%8,%9}, {%0,%1,%2,%3};\n"
        : "+f"(d[0]), "+f"(d[1]), "+f"(d[2]), "+f"(d[3])
        : "r"(__float_as_uint(a[0])), "r"(__float_as_uint(a[1])),
          "r"(__float_as_uint(a[2])), "r"(__float_as_uint(a[3])),
          "r"(__float_as_uint(b[0])), "r"(__float_as_uint(b[1])));
}

// ---------------------------------------------------------------------------
// tf32 MMA GEMM: C[m][n] = sum_k A[m][k] * W[n][k] + bias[n]
// Block tile 128x128, 8 warps (warp tile 64x32), k-chunk 16, 256 threads.
// Requires M%128==0, N%128==0, K%16==0.
// ---------------------------------------------------------------------------
#define GS 20   // smem row stride (floats): conflict-free fragment LDS

__global__ __launch_bounds__(256)
void gemm_tf32_kernel(const float* __restrict__ A, size_t sA,
                      const float* __restrict__ W, size_t sW,
                      const float* __restrict__ bias, size_t sB,
                      float* __restrict__ C, size_t sC,
                      int M, int N, int K)
{
    __shared__ float As[128 * GS];
    __shared__ float Ws[128 * GS];

    const int z = blockIdx.z;
    A    += (size_t)z * sA;
    W    += (size_t)z * sW;
    bias += (size_t)z * sB;
    C    += (size_t)z * sC;

    const int m0 = blockIdx.y * 128;
    const int n0 = blockIdx.x * 128;
    const int tid  = threadIdx.x;
    const int wid  = tid >> 5;
    const int lane = tid & 31;
    const int gid  = lane >> 2;   // groupID (row within m16 fragment)
    const int t4   = lane & 3;
    const int wm   = (wid & 1) * 64;
    const int wn   = (wid >> 1) * 32;

    float acc[4][4][4];
    #pragma unroll
    for (int a = 0; a < 4; a++)
        #pragma unroll
        for (int b = 0; b < 4; b++)
            #pragma unroll
            for (int c = 0; c < 4; c++) acc[a][b][c] = 0.f;

    const int ldrow = tid >> 2;        // 0..63
    const int ldq   = (tid & 3) * 4;   // 0,4,8,12

    for (int k0 = 0; k0 < K; k0 += 16) {
        __syncthreads();
        #pragma unroll
        for (int p = 0; p < 2; p++) {
            int row = ldrow + p * 64;
            float4 av = *(const float4*)&A[(size_t)(m0 + row) * K + k0 + ldq];
            float4 wv = *(const float4*)&W[(size_t)(n0 + row) * K + k0 + ldq];
            *(float4*)&As[row * GS + ldq] = f2tf32_4(av);
            *(float4*)&Ws[row * GS + ldq] = f2tf32_4(wv);
        }
        __syncthreads();

        #pragma unroll
        for (int kk = 0; kk < 2; kk++) {
            float afr[4][4];
            #pragma unroll
            for (int mt = 0; mt < 4; mt++) {
                int r = wm + mt * 16 + gid;
                int c = kk * 8 + t4;
                afr[mt][0] = As[r * GS + c];
                afr[mt][1] = As[(r + 8) * GS + c];
                afr[mt][2] = As[r * GS + c + 4];
                afr[mt][3] = As[(r + 8) * GS + c + 4];
            }
            float bfr[4][2];
            #pragma unroll
            for (int nt = 0; nt < 4; nt++) {
                int r = wn + nt * 8 + gid;
                int c = kk * 8 + t4;
                bfr[nt][0] = Ws[r * GS + c];
                bfr[nt][1] = Ws[r * GS + c + 4];
            }
            #pragma unroll
            for (int mt = 0; mt < 4; mt++)
                #pragma unroll
                for (int nt = 0; nt < 4; nt++)
                    mma_tf32(acc[mt][nt], afr[mt], bfr[nt]);
        }
    }

    #pragma unroll
    for (int mt = 0; mt < 4; mt++) {
        int m = m0 + wm + mt * 16 + gid;
        #pragma unroll
        for (int nt = 0; nt < 4; nt++) {
            int n = n0 + wn + nt * 8 + 2 * t4;
            float b0 = bias[n], b1 = bias[n + 1];
            float2 v0 = make_float2(acc[mt][nt][0] + b0, acc[mt][nt][1] + b1);
            float2 v1 = make_float2(acc[mt][nt][2] + b0, acc[mt][nt][3] + b1);
            *(float2*)&C[(size_t)m * N + n]       = v0;
            *(float2*)&C[(size_t)(m + 8) * N + n] = v1;
        }
    }
}

// ---------------------------------------------------------------------------
// Flash attention with tf32 MMA.
// grid: (T/64, H, G*B). block: 128 threads (4 warps).
// Each warp owns 16 q-rows; loop over S in 32-key chunks.
// Q held in register fragments; P staged through smem for the PV MMA.
// ---------------------------------------------------------------------------
#define KSTR 68   // K smem stride
#define VSTR 72   // V smem stride
#define PSTR 52   // P smem stride
#define QSTR 68   // Q staging stride (aliased with P region)

__global__ __launch_bounds__(128)
void flash_tf32_kernel(const float* __restrict__ qi,
                       const float* __restrict__ ki,
                       const float* __restrict__ vi,
                       float* __restrict__ ctx)
{
    __shared__ float Ks[32 * KSTR];
    __shared__ float Vs[32 * VSTR];
    __shared__ float QPs[64 * QSTR];   // Q staging, then P tiles

    const int zz = blockIdx.z;
    const int h  = blockIdx.y;
    const int t0 = blockIdx.x * 64;
    const size_t qbase = ((size_t)zz * Tq + t0) * Eq + (size_t)h * Dq;
    const size_t kbase = (size_t)zz * Sq * Eq + (size_t)h * Dq;

    const int tid  = threadIdx.x;
    const int wid  = tid >> 5;
    const int lane = tid & 31;
    const int gid  = lane >> 2;
    const int t4   = lane & 3;
    const int wrow = wid * 16;          // warp's q-row base within tile

    // ---- Stage Q tile [64 x 64] into smem (tf32-rounded) ----
    {
        const int row = tid >> 1;            // 0..63
        const int c4  = (tid & 1) * 8;       // two float4 groups per half-row pass
        #pragma unroll
        for (int p = 0; p < 2; p++) {
            int c = c4 + p * 4;
            float4 v = *(const float4*)&qi[qbase + (size_t)row * Eq + c * 4];
            *(float4*)&QPs[row * QSTR + c * 4] = f2tf32_4(v);
        }
        // remaining half of each row
        #pragma unroll
        for (int p = 0; p < 2; p++) {
            int c = c4 + p * 4 + 16 - 16; (void)c;
        }
    }
    // The above covered cols 0..63? row has 16 float4; tid&1 selects 8-float4 halves:
    // redo cleanly below to be safe.
    __syncthreads();
    {
        // full reload (simple, correct): 64 rows x 16 float4 = 1024, 128 thr x 8
        #pragma unroll
        for (int i = 0; i < 8; i++) {
            int idx = tid + i * 128;
            int row = idx >> 4;
            int c4  = idx & 15;
            float4 v = *(const float4*)&qi[qbase + (size_t)row * Eq + c4 * 4];
            *(float4*)&QPs[row * QSTR + c4 * 4] = f2tf32_4(v);
        }
    }
    __syncthreads();

    // ---- Preload Q fragments: Aq[kk 0..7][4] ----
    float Aq[8][4];
    #pragma unroll
    for (int kk = 0; kk < 8; kk++) {
        int r = wrow + gid;
        int c = kk * 8 + t4;
        Aq[kk][0] = QPs[r * QSTR + c];
        Aq[kk][1] = QPs[(r + 8) * QSTR + c];
        Aq[kk][2] = QPs[r * QSTR + c + 4];
        Aq[kk][3] = QPs[(r + 8) * QSTR + c + 4];
    }

    float out[8][4];
    #pragma unroll
    for (int j = 0; j < 8; j++)
        #pragma unroll
        for (int c = 0; c < 4; c++) out[j][c] = 0.f;
    float mrow[2] = {-1e30f, -1e30f};
    float lrow[2] = {0.f, 0.f};

    const float kappa = 0.125f * 1.44269504088896340736f;  // scale * log2(e)

    for (int s0 = 0; s0 < Sq; s0 += 32) {
        __syncthreads();   // Q frags loaded / previous PV reads done
        // ---- Load K,V chunk [32 x 64] (tf32-rounded) ----
        #pragma unroll
        for (int i = 0; i < 4; i++) {
            int idx = tid + i * 128;
            int row = idx >> 4;
            int c4  = idx & 15;
            size_t go = kbase + (size_t)(s0 + row) * Eq + c4 * 4;
            float4 kv = *(const float4*)&ki[go];
            float4 vv = *(const float4*)&vi[go];
            *(float4*)&Ks[row * KSTR + c4 * 4] = f2tf32_4(kv);
            *(float4*)&Vs[row * VSTR + c4 * 4] = f2tf32_4(vv);
        }
        __syncthreads();

        // ---- Scores: S[16 x 32] per warp via MMA ----
        float sc[4][4];
        #pragma unroll
        for (int j = 0; j < 4; j++)
            #pragma unroll
            for (int c = 0; c < 4; c++) sc[j][c] = 0.f;

        #pragma unroll
        for (int kk = 0; kk < 8; kk++) {
            #pragma unroll
            for (int j = 0; j < 4; j++) {
                float bfr[2];
                int key = j * 8 + gid;
                int d   = kk * 8 + t4;
                bfr[0] = Ks[key * KSTR + d];
                bfr[1] = Ks[key * KSTR + d + 4];
                mma_tf32(sc[j], Aq[kk], bfr);
            }
        }

        // ---- Online softmax (log2 domain) ----
        #pragma unroll
        for (int j = 0; j < 4; j++)
            #pragma unroll
            for (int c = 0; c < 4; c++) sc[j][c] *= kappa;

        float pv[4][4];
        #pragma unroll
        for (int r = 0; r < 2; r++) {
            float mx = -1e30f;
            #pragma unroll
            for (int j = 0; j < 4; j++)
                mx = fmaxf(mx, fmaxf(sc[j][2*r], sc[j][2*r + 1]));
            mx = fmaxf(mx, __shfl_xor_sync(0xffffffffu, mx, 1));
            mx = fmaxf(mx, __shfl_xor_sync(0xffffffffu, mx, 2));
            float mn = fmaxf(mrow[r], mx);
            float corr = exp2f(mrow[r] - mn);
            mrow[r] = mn;
            float rs = 0.f;
            #pragma unroll
            for (int j = 0; j < 4; j++) {
                float p0 = exp2f(sc[j][2*r]     - mn);
                float p1 = exp2f(sc[j][2*r + 1] - mn);
                pv[j][2*r]     = p0;
                pv[j][2*r + 1] = p1;
                rs += p0 + p1;
            }
            rs += __shfl_xor_sync(0xffffffffu, rs, 1);
            rs += __shfl_xor_sync(0xffffffffu, rs, 2);
            lrow[r] = lrow[r] * corr + rs;
            #pragma unroll
            for (int j = 0; j < 8; j++) {
                out[j][2*r]     *= corr;
                out[j][2*r + 1] *= corr;
            }
        }

        // ---- Store P (tf32) to smem ----
        #pragma unroll
        for (int j = 0; j < 4; j++) {
            int col = j * 8 + 2 * t4;
            *(float2*)&QPs[(wrow + gid) * PSTR + col] =
                make_float2(f2tf32(pv[j][0]), f2tf32(pv[j][1]));
            *(float2*)&QPs[(wrow + gid + 8) * PSTR + col] =
                make_float2(f2tf32(pv[j][2]), f2tf32(pv[j][3]));
        }
        __syncthreads();

        // ---- PV: out[16 x 64] += P[16 x 32] * V[32 x 64] ----
        #pragma unroll
        for (int kk = 0; kk < 4; kk++) {
            float afr[4];
            int r = wrow + gid;
            int c = kk * 8 + t4;
            afr[0] = QPs[r * PSTR + c];
            afr[1] = QPs[(r + 8) * PSTR + c];
            afr[2] = QPs[r * PSTR + c + 4];
            afr[3] = QPs[(r + 8) * PSTR + c + 4];
            #pragma unroll
            for (int j = 0; j < 8; j++) {
                float bfr[2];
                int key = kk * 8 + t4;
                int d   = j * 8 + gid;
                bfr[0] = Vs[key * VSTR + d];
                bfr[1] = Vs[(key + 4) * VSTR + d];
                mma_tf32(out[j], afr, bfr);
            }
        }
    }

    // ---- Normalize and write ----
    float inv0 = 1.0f / lrow[0];
    float inv1 = 1.0f / lrow[1];
    int r0 = wrow + gid;
    #pragma unroll
    for (int j = 0; j < 8; j++) {
        int col = j * 8 + 2 * t4;
        *(float2*)&ctx[qbase + (size_t)r0 * Eq + col] =
            make_float2(out[j][0] * inv0, out[j][1] * inv0);
        *(float2*)&ctx[qbase + (size_t)(r0 + 8) * Eq + col] =
            make_float2(out[j][2] * inv1, out[j][3] * inv1);
    }
}

// ---------------------------------------------------------------------------
// Permutes: interleaved group split / merge (s = t*G + g)
// ---------------------------------------------------------------------------
__global__ void group_q_kernel(const float* __restrict__ src, float* __restrict__ dst)
{
    int idx = blockIdx.x * 256 + threadIdx.x;
    int e = idx % Eq;
    int r = idx / Eq;
    int t = r % Tq;
    int gb = r / Tq;
    int b = gb % Bq;
    int g = gb / Bq;
    dst[idx] = src[((size_t)b * Sq + (size_t)t * Gq + g) * Eq + e];
}

__global__ void ungroup_kernel(const float* __restrict__ src, float* __restrict__ dst)
{
    int idx = blockIdx.x * 256 + threadIdx.x;
    int e = idx % Eq;
    int r = idx / Eq;
    int s = r % Sq;
    int b = r / Sq;
    int t = s / Gq;
    int g = s % Gq;
    dst[idx] = src[(((size_t)(g * Bq + b)) * Tq + t) * Eq + e];
}

// ---------------------------------------------------------------------------
// Launch
// ---------------------------------------------------------------------------
extern "C" void kernel_launch(void* const* d_in, const int* in_sizes, int n_in,
                              void* d_out, int out_size)
{
    const float* query = (const float*)d_in[0];
    const float* key_  = (const float*)d_in[1];
    const float* value = (const float*)d_in[2];
    const float* Wqg   = (const float*)d_in[3];
    const float* bqg   = (const float*)d_in[4];
    const float* Wk    = (const float*)d_in[5];
    const float* bk    = (const float*)d_in[6];
    const float* Wv    = (const float*)d_in[7];
    const float* bv    = (const float*)d_in[8];
    const float* Wq_in = (const float*)d_in[9];
    const float* bq_in = (const float*)d_in[10];
    const float* Wk_in = (const float*)d_in[11];
    const float* bk_in = (const float*)d_in[12];
    const float* Wv_in = (const float*)d_in[13];
    const float* bv_in = (const float*)d_in[14];
    const float* Wout  = (const float*)d_in[15];
    const float* bout  = (const float*)d_in[16];
    float* out = (float*)d_out;

    float *qproj, *kproj, *vproj, *qg, *qiP, *kiP, *viP, *ctx, *outg;
    cudaGetSymbolAddress((void**)&qproj, g_qproj);
    cudaGetSymbolAddress((void**)&kproj, g_kproj);
    cudaGetSymbolAddress((void**)&vproj, g_vproj);
    cudaGetSymbolAddress((void**)&qg,    g_qg);
    cudaGetSymbolAddress((void**)&qiP,   g_qi);
    cudaGetSymbolAddress((void**)&kiP,   g_ki);
    cudaGetSymbolAddress((void**)&viP,   g_vi);
    cudaGetSymbolAddress((void**)&ctx,   g_ctx);
    cudaGetSymbolAddress((void**)&outg,  g_outg);

    const dim3 blk(256);
    const size_t EE  = (size_t)Eq * Eq;
    const size_t BTE = (size_t)Bq * Tq * Eq;
    const size_t BSE = (size_t)Bq * Sq * Eq;

    // 1) Outer projections: [B*S, E] x [E, E]^T
    dim3 gproj(Eq / 128, (Bq * Sq) / 128, 1);
    gemm_tf32_kernel<<<gproj, blk>>>(query, 0, Wqg, 0, bqg, 0, qproj, 0, Bq*Sq, Eq, Eq);
    gemm_tf32_kernel<<<gproj, blk>>>(key_,  0, Wk,  0, bk,  0, kproj, 0, Bq*Sq, Eq, Eq);
    gemm_tf32_kernel<<<gproj, blk>>>(value, 0, Wv,  0, bv,  0, vproj, 0, Bq*Sq, Eq, Eq);

    // 2) Gather interleaved query groups
    group_q_kernel<<<(Gq * Bq * Tq * Eq) / 256, blk>>>(qproj, qg);

    // 3) Per-group inner projections
    dim3 gqi(Eq / 128, (Bq * Tq) / 128, Gq);
    gemm_tf32_kernel<<<gqi, blk>>>(qg, BTE, Wq_in, EE, bq_in, Eq, qiP, BTE, Bq*Tq, Eq, Eq);
    dim3 gki(Eq / 128, (Bq * Sq) / 128, Gq);
    gemm_tf32_kernel<<<gki, blk>>>(kproj, 0, Wk_in, EE, bk_in, Eq, kiP, BSE, Bq*Sq, Eq, Eq);
    gemm_tf32_kernel<<<gki, blk>>>(vproj, 0, Wv_in, EE, bv_in, Eq, viP, BSE, Bq*Sq, Eq, Eq);

    // 4) Attention
    dim3 gfa(Tq / 64, Hq, Bq * Gq);
    flash_tf32_kernel<<<gfa, dim3(128)>>>(qiP, kiP, viP, ctx);

    // 5) Output projection + scatter
    gemm_tf32_kernel<<<gqi, blk>>>(ctx, BTE, Wout, EE, bout, Eq, outg, BTE, Bq*Tq, Eq, Eq);
    ungroup_kernel<<<(Bq * Sq * Eq) / 256, blk>>>(outg, out);
}

// round 4
// speedup vs baseline: 3.1419x; 1.0689x over previous
#include <cuda_runtime.h>
#include <cstdint>

// Problem constants
#define Bq 2
#define Sq 2048
#define Eq 768
#define Hq 12
#define Gq 4
#define Dq 64
#define Tq 512   // Sq / Gq

#define EEc ((size_t)Eq * Eq)
#define BTEc ((size_t)Bq * Tq * Eq)
#define BSEc ((size_t)Bq * Sq * Eq)

// ---------------------------------------------------------------------------
// Scratch (device globals; no dynamic allocation allowed)
// ---------------------------------------------------------------------------
__device__ float g_wc[12 * EEc];     // composed weights: [q g0..3, k g0..3, v g0..3]
__device__ float g_bc[12 * Eq];      // composed biases
__device__ float g_zero[Eq];         // stays zero (never written)
__device__ float g_qi [Gq*Bq*Tq*Eq];
__device__ float g_ki [(size_t)Gq*Bq*Sq*Eq];
__device__ float g_vi [(size_t)Gq*Bq*Sq*Eq];
__device__ float g_ctx[Gq*Bq*Tq*Eq];

// ---------------------------------------------------------------------------
// tf32 helpers
// ---------------------------------------------------------------------------
__device__ __forceinline__ float f2tf32(float x) {
    uint32_t r;
    asm("cvt.rna.tf32.f32 %0, %1;" : "=r"(r) : "f"(x));
    return __uint_as_float(r);
}
__device__ __forceinline__ float4 f2tf32_4(float4 v) {
    return make_float4(f2tf32(v.x), f2tf32(v.y), f2tf32(v.z), f2tf32(v.w));
}
__device__ __forceinline__ void mma_tf32(float (&d)[4], const float a[4], const float b[2]) {
    asm volatile(
        "mma.sync.aligned.m16n8k8.row.col.f32.tf32.tf32.f32 "
        "{%0,%1,%2,%3}, {%4,%5,%6,%7}, {%8,%9}, {%0,%1,%2,%3};\n"
        : "+f"(d[0]), "+f"(d[1]), "+f"(d[2]), "+f"(d[3])
        : "r"(__float_as_uint(a[0])), "r"(__float_as_uint(a[1])),
          "r"(__float_as_uint(a[2])), "r"(__float_as_uint(a[3])),
          "r"(__float_as_uint(b[0])), "r"(__float_as_uint(b[1])));
}

// ---------------------------------------------------------------------------
// tf32 GEMM: C[m][n] = sum_k A[m][k] * W[n][k] + bias[n]
// Block 128 thr, tile 128m x 64n, warp tile 64x32, k-chunk 16, reg prefetch.
// amap=1: A row m gathered from query rows (b*Sq + t*Gq + z).
// cmap=1: C row m scattered to out rows (b*Sq + t*Gq + z).
// wtrans=1: W operand read as B[k][n] from row-major [K][N] (compose).
// z >= zSplit switches to A2/C2 bases (kv fusion).
// ---------------------------------------------------------------------------
#define GS 20

__global__ __launch_bounds__(128)
void gemm_tf32_kernel(const float* __restrict__ A, const float* __restrict__ A2,
                      size_t sA, int zSplit,
                      const float* __restrict__ W, size_t sW, int wtrans,
                      const float* __restrict__ bias, size_t sB,
                      float* __restrict__ C, float* __restrict__ C2, size_t sC,
                      int M, int N, int K, int amap, int cmap)
{
    __shared__ float As[128 * GS];
    __shared__ float Ws[64 * GS];

    const int z = blockIdx.z;
    const float* Ab = (z < zSplit) ? A + (size_t)z * sA : A2 + (size_t)(z - zSplit) * sA;
    float*       Cb = (z < zSplit) ? C + (size_t)z * sC : C2 + (size_t)(z - zSplit) * sC;
    const float* Wb = W + (size_t)z * sW;
    const float* bb = bias + (size_t)z * sB;

    const int m0 = blockIdx.y * 128;
    const int n0 = blockIdx.x * 64;
    const int tid  = threadIdx.x;
    const int wid  = tid >> 5;
    const int lane = tid & 31;
    const int gid  = lane >> 2;
    const int t4   = lane & 3;
    const int wm   = (wid & 1) * 64;
    const int wn   = (wid >> 1) * 32;

    float acc[4][4][4];
    #pragma unroll
    for (int a = 0; a < 4; a++)
        #pragma unroll
        for (int b = 0; b < 4; b++)
            #pragma unroll
            for (int c = 0; c < 4; c++) acc[a][b][c] = 0.f;

    float4 pa[4], pw[2];

    auto loadA = [&](int k0) {
        #pragma unroll
        for (int p = 0; p < 4; p++) {
            int idx = tid + p * 128;
            int row = m0 + (idx >> 2);
            int q = (idx & 3) * 4;
            size_t gr;
            if (amap) gr = (size_t)(row >> 9) * Sq + (size_t)(row & 511) * Gq + z;
            else      gr = (size_t)row;
            pa[p] = *(const float4*)&Ab[gr * (size_t)K + k0 + q];
        }
    };
    auto loadW = [&](int k0) {
        if (!wtrans) {
            #pragma unroll
            for (int p = 0; p < 2; p++) {
                int idx = tid + p * 128;
                int row = n0 + (idx >> 2);
                int q = (idx & 3) * 4;
                pw[p] = *(const float4*)&Wb[(size_t)row * K + k0 + q];
            }
        } else {
            #pragma unroll
            for (int p = 0; p < 2; p++) {
                int idx = tid + p * 128;
                int e  = idx >> 4;          // 0..15 (k within chunk)
                int jq = (idx & 15) * 4;    // 0..60 (n within tile)
                pw[p] = *(const float4*)&Wb[(size_t)(k0 + e) * N + n0 + jq];
            }
        }
    };
    auto storeT = [&]() {
        #pragma unroll
        for (int p = 0; p < 4; p++) {
            int idx = tid + p * 128;
            int row = idx >> 2;
            int q = (idx & 3) * 4;
            *(float4*)&As[row * GS + q] = f2tf32_4(pa[p]);
        }
        if (!wtrans) {
            #pragma unroll
            for (int p = 0; p < 2; p++) {
                int idx = tid + p * 128;
                int row = idx >> 2;
                int q = (idx & 3) * 4;
                *(float4*)&Ws[row * GS + q] = f2tf32_4(pw[p]);
            }
        } else {
            #pragma unroll
            for (int p = 0; p < 2; p++) {
                int idx = tid + p * 128;
                int e  = idx >> 4;
                int jq = (idx & 15) * 4;
                float4 v = f2tf32_4(pw[p]);
                Ws[(jq + 0) * GS + e] = v.x;
                Ws[(jq + 1) * GS + e] = v.y;
                Ws[(jq + 2) * GS + e] = v.z;
                Ws[(jq + 3) * GS + e] = v.w;
            }
        }
    };

    loadA(0); loadW(0);

    for (int k0 = 0; k0 < K; k0 += 16) {
        storeT();
        __syncthreads();
        if (k0 + 16 < K) { loadA(k0 + 16); loadW(k0 + 16); }

        #pragma unroll
        for (int kk = 0; kk < 2; kk++) {
            float afr[4][4];
            #pragma unroll
            for (int mt = 0; mt < 4; mt++) {
                int r = wm + mt * 16 + gid;
                int c = kk * 8 + t4;
                afr[mt][0] = As[r * GS + c];
                afr[mt][1] = As[(r + 8) * GS + c];
                afr[mt][2] = As[r * GS + c + 4];
                afr[mt][3] = As[(r + 8) * GS + c + 4];
            }
            float bfr[4][2];
            #pragma unroll
            for (int nt = 0; nt < 4; nt++) {
                int r = wn + nt * 8 + gid;
                int c = kk * 8 + t4;
                bfr[nt][0] = Ws[r * GS + c];
                bfr[nt][1] = Ws[r * GS + c + 4];
            }
            #pragma unroll
            for (int mt = 0; mt < 4; mt++)
                #pragma unroll
                for (int nt = 0; nt < 4; nt++)
                    mma_tf32(acc[mt][nt], afr[mt], bfr[nt]);
        }
        __syncthreads();
    }

    #pragma unroll
    for (int mt = 0; mt < 4; mt++) {
        int m = m0 + wm + mt * 16 + gid;
        size_t r0, r1;
        if (cmap) {
            r0 = (size_t)(m >> 9) * Sq + (size_t)(m & 511) * Gq + z;
            r1 = (size_t)((m + 8) >> 9) * Sq + (size_t)((m + 8) & 511) * Gq + z;
        } else {
            r0 = (size_t)m; r1 = (size_t)(m + 8);
        }
        #pragma unroll
        for (int nt = 0; nt < 4; nt++) {
            int n = n0 + wn + nt * 8 + 2 * t4;
            float b0 = bb[n], b1 = bb[n + 1];
            *(float2*)&Cb[r0 * N + n] = make_float2(acc[mt][nt][0] + b0, acc[mt][nt][1] + b1);
            *(float2*)&Cb[r1 * N + n] = make_float2(acc[mt][nt][2] + b0, acc[mt][nt][3] + b1);
        }
    }
}

// ---------------------------------------------------------------------------
// Bias compose: bc[g][f] = dot(Win[g][f][:], b_outer) + b_in[g][f]
// grid (Eq/8, G), block 256: one warp per output row.
// ---------------------------------------------------------------------------
__global__ void biascomp_kernel(const float* __restrict__ Win,
                                const float* __restrict__ bo,
                                const float* __restrict__ bi,
                                float* __restrict__ bc)
{
    int g = blockIdx.y;
    int f = blockIdx.x * 8 + (threadIdx.x >> 5);
    int lane = threadIdx.x & 31;
    const float* wr = Win + (size_t)g * EEc + (size_t)f * Eq;
    float s = 0.f;
    for (int j = lane * 4; j < Eq; j += 128) {
        float4 w = *(const float4*)&wr[j];
        float4 b = *(const float4*)&bo[j];
        s += w.x*b.x + w.y*b.y + w.z*b.z + w.w*b.w;
    }
    #pragma unroll
    for (int o = 16; o; o >>= 1) s += __shfl_xor_sync(0xffffffffu, s, o);
    if (lane == 0) bc[(size_t)g * Eq + f] = s + bi[(size_t)g * Eq + f];
}

// ---------------------------------------------------------------------------
// Flash attention, tf32 MMA, 64-key chunks.
// grid (T/64, H, G*B), block 128 (4 warps, 16 q-rows each). Dynamic smem.
// ---------------------------------------------------------------------------
#define KSTR 68
#define VSTR 72
#define QSTR 68
#define FLASH_SMEM ((64*KSTR + 64*VSTR + 64*QSTR) * 4)

__global__ __launch_bounds__(128)
void flash_tf32_kernel(const float* __restrict__ qi,
                       const float* __restrict__ ki,
                       const float* __restrict__ vi,
                       float* __restrict__ ctx)
{
    extern __shared__ float sm[];
    float* Ks  = sm;
    float* Vs  = Ks + 64 * KSTR;
    float* QPs = Vs + 64 * VSTR;   // Q staging, then P tiles

    const int zz = blockIdx.z;
    const int h  = blockIdx.y;
    const int t0 = blockIdx.x * 64;
    const size_t qbase = ((size_t)zz * Tq + t0) * Eq + (size_t)h * Dq;
    const size_t kbase = (size_t)zz * Sq * Eq + (size_t)h * Dq;

    const int tid  = threadIdx.x;
    const int wid  = tid >> 5;
    const int lane = tid & 31;
    const int gid  = lane >> 2;
    const int t4   = lane & 3;
    const int wrow = wid * 16;

    // Stage Q tile [64 x 64] (tf32)
    #pragma unroll
    for (int i = 0; i < 8; i++) {
        int idx = tid + i * 128;
        int row = idx >> 4;
        int c4  = idx & 15;
        float4 v = *(const float4*)&qi[qbase + (size_t)row * Eq + c4 * 4];
        *(float4*)&QPs[row * QSTR + c4 * 4] = f2tf32_4(v);
    }
    __syncthreads();

    float Aq[8][4];
    #pragma unroll
    for (int kk = 0; kk < 8; kk++) {
        int r = wrow + gid;
        int c = kk * 8 + t4;
        Aq[kk][0] = QPs[r * QSTR + c];
        Aq[kk][1] = QPs[(r + 8) * QSTR + c];
        Aq[kk][2] = QPs[r * QSTR + c + 4];
        Aq[kk][3] = QPs[(r + 8) * QSTR + c + 4];
    }

    float out[8][4];
    #pragma unroll
    for (int j = 0; j < 8; j++)
        #pragma unroll
        for (int c = 0; c < 4; c++) out[j][c] = 0.f;
    float mrow[2] = {-1e30f, -1e30f};
    float lrow[2] = {0.f, 0.f};
    const float kappa = 0.125f * 1.44269504088896340736f;

    for (int s0 = 0; s0 < Sq; s0 += 64) {
        __syncthreads();
        // Load K,V chunk [64 x 64]
        #pragma unroll
        for (int i = 0; i < 8; i++) {
            int idx = tid + i * 128;
            int row = idx >> 4;
            int c4  = idx & 15;
            size_t go = kbase + (size_t)(s0 + row) * Eq + c4 * 4;
            float4 kv = *(const float4*)&ki[go];
            float4 vv = *(const float4*)&vi[go];
            *(float4*)&Ks[row * KSTR + c4 * 4] = f2tf32_4(kv);
            *(float4*)&Vs[row * VSTR + c4 * 4] = f2tf32_4(vv);
        }
        __syncthreads();

        // Scores S[16 x 64] per warp
        float sc[8][4];
        #pragma unroll
        for (int j = 0; j < 8; j++)
            #pragma unroll
            for (int c = 0; c < 4; c++) sc[j][c] = 0.f;
        #pragma unroll
        for (int kk = 0; kk < 8; kk++) {
            #pragma unroll
            for (int j = 0; j < 8; j++) {
                float bfr[2];
                int key = j * 8 + gid;
                int d   = kk * 8 + t4;
                bfr[0] = Ks[key * KSTR + d];
                bfr[1] = Ks[key * KSTR + d + 4];
                mma_tf32(sc[j], Aq[kk], bfr);
            }
        }

        #pragma unroll
        for (int j = 0; j < 8; j++)
            #pragma unroll
            for (int c = 0; c < 4; c++) sc[j][c] *= kappa;

        // Online softmax (log2 domain); exp written in place into sc
        #pragma unroll
        for (int r = 0; r < 2; r++) {
            float mx = -1e30f;
            #pragma unroll
            for (int j = 0; j < 8; j++)
                mx = fmaxf(mx, fmaxf(sc[j][2*r], sc[j][2*r + 1]));
            mx = fmaxf(mx, __shfl_xor_sync(0xffffffffu, mx, 1));
            mx = fmaxf(mx, __shfl_xor_sync(0xffffffffu, mx, 2));
            float mn = fmaxf(mrow[r], mx);
            float corr = exp2f(mrow[r] - mn);
            mrow[r] = mn;
            float rs = 0.f;
            #pragma unroll
            for (int j = 0; j < 8; j++) {
                float p0 = exp2f(sc[j][2*r]     - mn);
                float p1 = exp2f(sc[j][2*r + 1] - mn);
                sc[j][2*r]     = p0;
                sc[j][2*r + 1] = p1;
                rs += p0 + p1;
            }
            rs += __shfl_xor_sync(0xffffffffu, rs, 1);
            rs += __shfl_xor_sync(0xffffffffu, rs, 2);
            lrow[r] = lrow[r] * corr + rs;
            #pragma unroll
            for (int j = 0; j < 8; j++) {
                out[j][2*r]     *= corr;
                out[j][2*r + 1] *= corr;
            }
        }

        // Store P [16 x 64] (own warp's rows only)
        #pragma unroll
        for (int j = 0; j < 8; j++) {
            int col = j * 8 + 2 * t4;
            *(float2*)&QPs[(wrow + gid) * QSTR + col] =
                make_float2(f2tf32(sc[j][0]), f2tf32(sc[j][1]));
            *(float2*)&QPs[(wrow + gid + 8) * QSTR + col] =
                make_float2(f2tf32(sc[j][2]), f2tf32(sc[j][3]));
        }
        __syncwarp();

        // PV: out[16 x 64] += P[16 x 64] * V[64 x 64]
        #pragma unroll
        for (int kk = 0; kk < 8; kk++) {
            float afr[4];
            int r = wrow + gid;
            int c = kk * 8 + t4;
            afr[0] = QPs[r * QSTR + c];
            afr[1] = QPs[(r + 8) * QSTR + c];
            afr[2] = QPs[r * QSTR + c + 4];
            afr[3] = QPs[(r + 8) * QSTR + c + 4];
            #pragma unroll
            for (int j = 0; j < 8; j++) {
                float bfr[2];
                int key = kk * 8 + t4;
                int d   = j * 8 + gid;
                bfr[0] = Vs[key * VSTR + d];
                bfr[1] = Vs[(key + 4) * VSTR + d];
                mma_tf32(out[j], afr, bfr);
            }
        }
    }

    float inv0 = 1.0f / lrow[0];
    float inv1 = 1.0f / lrow[1];
    int r0 = wrow + gid;
    #pragma unroll
    for (int j = 0; j < 8; j++) {
        int col = j * 8 + 2 * t4;
        *(float2*)&ctx[qbase + (size_t)r0 * Eq + col] =
            make_float2(out[j][0] * inv0, out[j][1] * inv0);
        *(float2*)&ctx[qbase + (size_t)(r0 + 8) * Eq + col] =
            make_float2(out[j][2] * inv1, out[j][3] * inv1);
    }
}

// ---------------------------------------------------------------------------
// Launch
// ---------------------------------------------------------------------------
extern "C" void kernel_launch(void* const* d_in, const int* in_sizes, int n_in,
                              void* d_out, int out_size)
{
    const float* query = (const float*)d_in[0];
    const float* key_  = (const float*)d_in[1];
    const float* value = (const float*)d_in[2];
    const float* Wqg   = (const float*)d_in[3];
    const float* bqg   = (const float*)d_in[4];
    const float* Wk    = (const float*)d_in[5];
    const float* bk    = (const float*)d_in[6];
    const float* Wv    = (const float*)d_in[7];
    const float* bv    = (const float*)d_in[8];
    const float* Wq_in = (const float*)d_in[9];
    const float* bq_in = (const float*)d_in[10];
    const float* Wk_in = (const float*)d_in[11];
    const float* bk_in = (const float*)d_in[12];
    const float* Wv_in = (const float*)d_in[13];
    const float* bv_in = (const float*)d_in[14];
    const float* Wout  = (const float*)d_in[15];
    const float* bout  = (const float*)d_in[16];
    float* out = (float*)d_out;

    float *wc, *bc, *zero, *qiP, *kiP, *viP, *ctx;
    cudaGetSymbolAddress((void**)&wc,   g_wc);
    cudaGetSymbolAddress((void**)&bc,   g_bc);
    cudaGetSymbolAddress((void**)&zero, g_zero);
    cudaGetSymbolAddress((void**)&qiP,  g_qi);
    cudaGetSymbolAddress((void**)&kiP,  g_ki);
    cudaGetSymbolAddress((void**)&viP,  g_vi);
    cudaGetSymbolAddress((void**)&ctx,  g_ctx);

    cudaFuncSetAttribute(flash_tf32_kernel,
                         cudaFuncAttributeMaxDynamicSharedMemorySize, FLASH_SMEM);

    // 1) Bias compose: bc = Win @ b_outer + b_in   (12 rows of 768)
    dim3 bcg(Eq / 8, Gq);
    biascomp_kernel<<<bcg, 256>>>(Wq_in, bqg, bq_in, bc);
    biascomp_kernel<<<bcg, 256>>>(Wk_in, bk,  bk_in, bc + 4 * Eq);
    biascomp_kernel<<<bcg, 256>>>(Wv_in, bv,  bv_in, bc + 8 * Eq);

    // 2) Weight compose: Wc[g] = Win[g] @ Wouter  (wtrans path)
    dim3 cg(Eq / 64, Eq / 128, Gq);
    gemm_tf32_kernel<<<cg, 128>>>(Wq_in, nullptr, EEc, 99, Wqg, 0, 1,
                                  zero, 0, wc, nullptr, EEc, Eq, Eq, Eq, 0, 0);
    gemm_tf32_kernel<<<cg, 128>>>(Wk_in, nullptr, EEc, 99, Wk, 0, 1,
                                  zero, 0, wc + 4 * EEc, nullptr, EEc, Eq, Eq, Eq, 0, 0);
    gemm_tf32_kernel<<<cg, 128>>>(Wv_in, nullptr, EEc, 99, Wv, 0, 1,
                                  zero, 0, wc + 8 * EEc, nullptr, EEc, Eq, Eq, Eq, 0, 0);

    // 3) qi = gather_g(query) @ Wc_q[g].T + bc_q[g]    (amap=1)
    dim3 gqi(Eq / 64, (Bq * Tq) / 128, Gq);
    gemm_tf32_kernel<<<gqi, 128>>>(query, nullptr, 0, 99, wc, EEc, 0,
                                   bc, Eq, qiP, nullptr, BTEc,
                                   Bq * Tq, Eq, Eq, 1, 0);

    // 4) ki/vi fused: z<4 -> key@Wc_k[g], z>=4 -> value@Wc_v[g]
    dim3 gkv(Eq / 64, (Bq * Sq) / 128, 2 * Gq);
    gemm_tf32_kernel<<<gkv, 128>>>(key_, value, 0, Gq, wc + 4 * EEc, EEc, 0,
                                   bc + 4 * Eq, Eq, kiP, viP, BSEc,
                                   Bq * Sq, Eq, Eq, 0, 0);

    // 5) Attention
    dim3 gfa(Tq / 64, Hq, Bq * Gq);
    flash_tf32_kernel<<<gfa, 128, FLASH_SMEM>>>(qiP, kiP, viP, ctx);

    // 6) out = scatter_g(ctx @ Wout[g].T + bout[g])    (cmap=1)
    gemm_tf32_kernel<<<gqi, 128>>>(ctx, nullptr, BTEc, 99, Wout, EEc, 0,
                                   bout, Eq, out, nullptr, 0,
                                   Bq * Tq, Eq, Eq, 0, 1);
}